// round 1
// baseline (speedup 1.0000x reference)
#include <cuda_runtime.h>
#include <cstdint>
#include <cstddef>

// ---------------------------------------------------------------------------
// SpikingMLP: x[T,B,N,C] -> fc1 -> BN -> LIF -> fc2 -> BN -> LIF -> (+x)
// T=4 B=16 N=1024 C=512 H=2048.  All fp32, deterministic (no float atomics).
// ---------------------------------------------------------------------------

namespace {
constexpr int T_ = 4, B_ = 16, N_ = 1024, C_ = 512, H_ = 2048;
constexpr int M_ = T_ * B_ * N_;      // 65536 GEMM rows
constexpr int ROWS_ = B_ * N_;        // 16384 spatial rows per timestep
constexpr int RB_ = M_ / 128;         // 512 rowblocks (per-CTA stat partials)
constexpr float EPS_ = 1e-5f;
}

// Scratch (static __device__ to satisfy no-alloc rules)
__device__ float g_y[(size_t)M_ * H_];     // 512 MB  fc1 output
__device__ float g_s[(size_t)M_ * H_];     // 512 MB  spikes 1
__device__ float g_z[(size_t)M_ * C_];     // 128 MB  fc2 output
__device__ float g_p1s[RB_ * H_];
__device__ float g_p1q[RB_ * H_];
__device__ float g_p2s[RB_ * C_];
__device__ float g_p2q[RB_ * C_];
__device__ float g_mean1[H_], g_sc1[H_];
__device__ float g_mean2[C_], g_sc2[C_];

// ---------------------------------------------------------------------------
// NT SGEMM:  C[m,n] = sum_k A[m,k] * Bw[n,k] + bias[n]
// A: [M,K] row-major, Bw: [N,K] row-major. 128x128x16 tile, 8x8 micro-tile.
// Also emits per-(rowblock, column) partial sum / sum-of-squares for BN stats
// (deterministic: each (blockIdx.y, n) written by exactly one CTA).
// ---------------------------------------------------------------------------
__global__ __launch_bounds__(256) void gemm_nt_stats(
    const float* __restrict__ A, const float* __restrict__ Bw,
    const float* __restrict__ bias, float* __restrict__ Cout,
    float* __restrict__ psum, float* __restrict__ psq,
    int K, int N)
{
    __shared__ float As[16][128];
    __shared__ float Bs[16][128];
    __shared__ float red[16][128];

    const int tid = threadIdx.x;
    const int tx = tid & 15;
    const int ty = tid >> 4;
    const int n0 = blockIdx.x * 128;
    const int m0 = blockIdx.y * 128;

    const float* Ap = A + (size_t)m0 * K;
    const float* Bp = Bw + (size_t)n0 * K;

    float acc[8][8];
#pragma unroll
    for (int i = 0; i < 8; ++i)
#pragma unroll
        for (int j = 0; j < 8; ++j) acc[i][j] = 0.f;

    for (int k0 = 0; k0 < K; k0 += 16) {
#pragma unroll
        for (int it = 0; it < 2; ++it) {
            int idx = tid + it * 256;
            int row = idx >> 2;          // 0..127
            int kq  = (idx & 3) << 2;    // 0,4,8,12
            float4 av = *reinterpret_cast<const float4*>(Ap + (size_t)row * K + k0 + kq);
            As[kq + 0][row] = av.x; As[kq + 1][row] = av.y;
            As[kq + 2][row] = av.z; As[kq + 3][row] = av.w;
            float4 bv = *reinterpret_cast<const float4*>(Bp + (size_t)row * K + k0 + kq);
            Bs[kq + 0][row] = bv.x; Bs[kq + 1][row] = bv.y;
            Bs[kq + 2][row] = bv.z; Bs[kq + 3][row] = bv.w;
        }
        __syncthreads();
#pragma unroll
        for (int k = 0; k < 16; ++k) {
            float a[8], b[8];
            *reinterpret_cast<float4*>(a)     = *reinterpret_cast<const float4*>(&As[k][ty * 8]);
            *reinterpret_cast<float4*>(a + 4) = *reinterpret_cast<const float4*>(&As[k][ty * 8 + 4]);
            *reinterpret_cast<float4*>(b)     = *reinterpret_cast<const float4*>(&Bs[k][tx * 8]);
            *reinterpret_cast<float4*>(b + 4) = *reinterpret_cast<const float4*>(&Bs[k][tx * 8 + 4]);
#pragma unroll
            for (int i = 0; i < 8; ++i)
#pragma unroll
                for (int j = 0; j < 8; ++j)
                    acc[i][j] += a[i] * b[j];
        }
        __syncthreads();
    }

    float bvals[8];
#pragma unroll
    for (int j = 0; j < 8; ++j) bvals[j] = bias[n0 + tx * 8 + j];

    float cs[8], cq[8];
#pragma unroll
    for (int j = 0; j < 8; ++j) { cs[j] = 0.f; cq[j] = 0.f; }

#pragma unroll
    for (int i = 0; i < 8; ++i) {
        float rowv[8];
#pragma unroll
        for (int j = 0; j < 8; ++j) {
            float v = acc[i][j] + bvals[j];
            rowv[j] = v;
            cs[j] += v;
            cq[j] += v * v;
        }
        float* outp = Cout + (size_t)(m0 + ty * 8 + i) * N + n0 + tx * 8;
        *reinterpret_cast<float4*>(outp)     = make_float4(rowv[0], rowv[1], rowv[2], rowv[3]);
        *reinterpret_cast<float4*>(outp + 4) = make_float4(rowv[4], rowv[5], rowv[6], rowv[7]);
    }

    // CTA-level column reduction of partial sum / sumsq (deterministic)
#pragma unroll
    for (int j = 0; j < 8; ++j) red[ty][tx * 8 + j] = cs[j];
    __syncthreads();
    if (tid < 128) {
        float s = 0.f;
#pragma unroll
        for (int r = 0; r < 16; ++r) s += red[r][tid];
        psum[(size_t)blockIdx.y * N + n0 + tid] = s;
    }
    __syncthreads();
#pragma unroll
    for (int j = 0; j < 8; ++j) red[ty][tx * 8 + j] = cq[j];
    __syncthreads();
    if (tid < 128) {
        float s = 0.f;
#pragma unroll
        for (int r = 0; r < 16; ++r) s += red[r][tid];
        psq[(size_t)blockIdx.y * N + n0 + tid] = s;
    }
}

// ---------------------------------------------------------------------------
// Reduce rowblock partials -> per-channel mean and gamma/sqrt(var+eps).
// fp64 accumulation keeps the reduction discrepancy vs JAX tiny (~1e-7 rel).
// ---------------------------------------------------------------------------
__global__ void finalize_stats(const float* __restrict__ psum, const float* __restrict__ psq,
                               const float* __restrict__ gamma,
                               float* __restrict__ meanOut, float* __restrict__ scOut, int N)
{
    int n = blockIdx.x * blockDim.x + threadIdx.x;
    if (n >= N) return;
    double s = 0.0, q = 0.0;
    for (int r = 0; r < RB_; ++r) {
        s += (double)psum[(size_t)r * N + n];
        q += (double)psq[(size_t)r * N + n];
    }
    const double inv = 1.0 / (double)M_;
    double dm = s * inv;
    float mean = (float)dm;
    float var  = (float)(q * inv - dm * dm);
    meanOut[n] = mean;
    scOut[n]   = gamma[n] / sqrtf(var + EPS_);
}

// ---------------------------------------------------------------------------
// Fused BN(apply) + 4-step LIF (+ optional residual add).
// idx = row*CH + h addresses the t=0 plane; timestep stride = ROWS_*CH.
// LIF: v = v + (y - v)/2 ; spike = (v >= 1) ; v = spike ? 0 : v
// ---------------------------------------------------------------------------
template <int CH, bool RES>
__global__ __launch_bounds__(256) void bn_lif_kernel(
    const float* __restrict__ y,
    const float* __restrict__ mean, const float* __restrict__ sc,
    const float* __restrict__ beta,
    const float* __restrict__ resid,
    float* __restrict__ outp)
{
    const long long idx = (long long)blockIdx.x * blockDim.x + threadIdx.x;
    if (idx >= (long long)ROWS_ * CH) return;
    const int h = (int)(idx & (CH - 1));
    const float m  = mean[h];
    const float s  = sc[h];
    const float bt = beta[h];
    const size_t base = (size_t)idx;
    const size_t stride = (size_t)ROWS_ * CH;

    float v = 0.f;
#pragma unroll
    for (int t = 0; t < T_; ++t) {
        const size_t off = base + (size_t)t * stride;
        float yv = (y[off] - m) * s + bt;
        v = v + (yv - v) * 0.5f;
        float sp = (v >= 1.0f) ? 1.0f : 0.0f;
        if (RES) outp[off] = sp + resid[off];
        else     outp[off] = sp;
        v = (v >= 1.0f) ? 0.0f : v;
    }
}

// ---------------------------------------------------------------------------
extern "C" void kernel_launch(void* const* d_in, const int* in_sizes, int n_in,
                              void* d_out, int out_size)
{
    (void)in_sizes; (void)n_in; (void)out_size;
    const float* x     = (const float*)d_in[0];
    const float* fc1_w = (const float*)d_in[1];
    const float* fc1_b = (const float*)d_in[2];
    const float* bn1_g = (const float*)d_in[3];
    const float* bn1_b = (const float*)d_in[4];
    const float* fc2_w = (const float*)d_in[5];
    const float* fc2_b = (const float*)d_in[6];
    const float* bn2_g = (const float*)d_in[7];
    const float* bn2_b = (const float*)d_in[8];
    float* out = (float*)d_out;

    float *y, *s, *z, *p1s, *p1q, *p2s, *p2q, *mean1, *sc1, *mean2, *sc2;
    cudaGetSymbolAddress((void**)&y,    g_y);
    cudaGetSymbolAddress((void**)&s,    g_s);
    cudaGetSymbolAddress((void**)&z,    g_z);
    cudaGetSymbolAddress((void**)&p1s,  g_p1s);
    cudaGetSymbolAddress((void**)&p1q,  g_p1q);
    cudaGetSymbolAddress((void**)&p2s,  g_p2s);
    cudaGetSymbolAddress((void**)&p2q,  g_p2q);
    cudaGetSymbolAddress((void**)&mean1, g_mean1);
    cudaGetSymbolAddress((void**)&sc1,   g_sc1);
    cudaGetSymbolAddress((void**)&mean2, g_mean2);
    cudaGetSymbolAddress((void**)&sc2,   g_sc2);

    // fc1 + BN1 stats
    gemm_nt_stats<<<dim3(H_ / 128, M_ / 128), 256>>>(x, fc1_w, fc1_b, y, p1s, p1q, C_, H_);
    finalize_stats<<<H_ / 256, 256>>>(p1s, p1q, bn1_g, mean1, sc1, H_);
    // BN1 apply + LIF1 -> spikes
    bn_lif_kernel<H_, false><<<(ROWS_ * H_) / 256, 256>>>(y, mean1, sc1, bn1_b, nullptr, s);
    // fc2 + BN2 stats
    gemm_nt_stats<<<dim3(C_ / 128, M_ / 128), 256>>>(s, fc2_w, fc2_b, z, p2s, p2q, H_, C_);
    finalize_stats<<<C_ / 256, 256>>>(p2s, p2q, bn2_g, mean2, sc2, C_);
    // BN2 apply + LIF2 + residual -> out
    bn_lif_kernel<C_, true><<<(ROWS_ * C_) / 256, 256>>>(z, mean2, sc2, bn2_b, x, out);
}